// round 1
// baseline (speedup 1.0000x reference)
#include <cuda_runtime.h>
#include <cuda_bf16.h>

// y[b, f*C + c] = sum_hw x[b,c,hw] * kern[f,c,hw]
// B=256, F=16, C=256, HW=1024
// Grid: (C=256, B/BT=2). Block: 128 threads.
// Each block: one c, a 128-row b-tile, full F=16, K=1024 in chunks of 32.
// Thread tile: 4b x 4f accumulators in registers.

#define B_DIM 256
#define F_DIM 16
#define C_DIM 256
#define HW_DIM 1024

#define BT 128     // b-tile per block
#define KC 32      // k-chunk staged in shared
#define THREADS 128

__global__ __launch_bounds__(THREADS, 8)
void spatial_emb_kernel(const float* __restrict__ x,
                        const float* __restrict__ kern,
                        float* __restrict__ out) {
    const int c  = blockIdx.x;        // 0..255
    const int bt = blockIdx.y;        // 0..1
    const int t  = threadIdx.x;       // 0..127
    const int tb = t & 31;            // b-group within tile (0..31) -> b = tb*4..tb*4+3
    const int tf = t >> 5;            // f-group (0..3) -> f = tf*4..tf*4+3

    // Transposed shared tiles: [k][m] so fragment reads are contiguous LDS.128.
    __shared__ float xs[KC][BT];      // 16 KB
    __shared__ float ks[KC][F_DIM];   // 2 KB

    // Global load roles:
    //  - x: thread t loads row b = bt*BT + t, 32 contiguous floats per chunk (one full 128B line).
    //  - kern: thread t loads f = t>>3, 4 floats at hw offset (t&7)*4.
    const int b_row = bt * BT + t;
    const float* xrow = x + ((size_t)b_row * C_DIM + c) * HW_DIM;
    const int lf = t >> 3;            // 0..15
    const int lh = (t & 7) * 4;       // 0,4,...,28
    const float* krow = kern + ((size_t)lf * C_DIM + c) * HW_DIM;

    float acc[4][4];
    #pragma unroll
    for (int i = 0; i < 4; i++)
        #pragma unroll
        for (int j = 0; j < 4; j++)
            acc[i][j] = 0.0f;

    for (int k0 = 0; k0 < HW_DIM; k0 += KC) {
        // Stage loads in registers first (keeps the global loads batched / MLP high)
        float4 xv[8];
        #pragma unroll
        for (int q = 0; q < 8; q++)
            xv[q] = *(const float4*)(xrow + k0 + q * 4);
        float4 kv = *(const float4*)(krow + k0 + lh);

        __syncthreads();   // protect previous iteration's reads before overwrite

        #pragma unroll
        for (int q = 0; q < 8; q++) {
            xs[q * 4 + 0][t] = xv[q].x;
            xs[q * 4 + 1][t] = xv[q].y;
            xs[q * 4 + 2][t] = xv[q].z;
            xs[q * 4 + 3][t] = xv[q].w;
        }
        ks[lh + 0][lf] = kv.x;
        ks[lh + 1][lf] = kv.y;
        ks[lh + 2][lf] = kv.z;
        ks[lh + 3][lf] = kv.w;

        __syncthreads();

        #pragma unroll
        for (int k = 0; k < KC; k++) {
            float4 a = *(const float4*)&xs[k][tb * 4];
            float4 b = *(const float4*)&ks[k][tf * 4];
            acc[0][0] += a.x * b.x;  acc[0][1] += a.x * b.y;
            acc[0][2] += a.x * b.z;  acc[0][3] += a.x * b.w;
            acc[1][0] += a.y * b.x;  acc[1][1] += a.y * b.y;
            acc[1][2] += a.y * b.z;  acc[1][3] += a.y * b.w;
            acc[2][0] += a.z * b.x;  acc[2][1] += a.z * b.y;
            acc[2][2] += a.z * b.z;  acc[2][3] += a.z * b.w;
            acc[3][0] += a.w * b.x;  acc[3][1] += a.w * b.y;
            acc[3][2] += a.w * b.z;  acc[3][3] += a.w * b.w;
        }
    }

    // out[b, f*C + c], b = bt*BT + tb*4 + i, f = tf*4 + j
    #pragma unroll
    for (int i = 0; i < 4; i++) {
        const int b = bt * BT + tb * 4 + i;
        float* orow = out + (size_t)b * (F_DIM * C_DIM) + c;
        #pragma unroll
        for (int j = 0; j < 4; j++) {
            const int f = tf * 4 + j;
            orow[(size_t)f * C_DIM] = acc[i][j];
        }
    }
}

extern "C" void kernel_launch(void* const* d_in, const int* in_sizes, int n_in,
                              void* d_out, int out_size) {
    const float* x    = (const float*)d_in[0];
    const float* kern = (const float*)d_in[1];
    float* out        = (float*)d_out;

    dim3 grid(C_DIM, B_DIM / BT);   // (256, 2)
    spatial_emb_kernel<<<grid, THREADS>>>(x, kern, out);
}